// round 3
// baseline (speedup 1.0000x reference)
#include <cuda_runtime.h>
#include <cstdint>

// Problem constants (shapes fixed by the dataset)
#define Dd 64
#define Rr 8
#define MAXN 100000
#define MAXE 3200000

// Scratch (allocation is forbidden -> device globals). 256B-aligned: we issue
// float4 stores and red.global.add.v4.f32 against these.
__device__ __align__(256) float g_sums[(size_t)MAXN * Rr * Dd]; // 204.8 MB
__device__ __align__(256) float g_cnt[MAXN * Rr];               // counts -> inv
__device__ __align__(256) float g_h0[MAXN * Dd];                // layer-0 input
__device__ __align__(256) float g_h1[MAXN * Dd];                // layer-1 out

// ---------------------------------------------------------------------------
__global__ void zero_kernel(float* __restrict__ p, size_t n4) {
    size_t i = (size_t)blockIdx.x * blockDim.x + threadIdx.x;
    size_t stride = (size_t)gridDim.x * blockDim.x;
    float4 z = make_float4(0.f, 0.f, 0.f, 0.f);
    float4* p4 = (float4*)p;
    for (; i < n4; i += stride) p4[i] = z;
}

// h0[i,:] = emb[x[i],:]   (x is int32 — JAX x64 is disabled by default)
__global__ void gather_kernel(const float* __restrict__ emb,
                              const int* __restrict__ x,
                              float* __restrict__ h0, int n) {
    int total = n * (Dd / 4);
    int stride = gridDim.x * blockDim.x;
    for (int i = blockIdx.x * blockDim.x + threadIdx.x; i < total; i += stride) {
        int node = i >> 4;          // Dd/4 = 16 float4 per row
        int q    = i & 15;
        int s = x[node];
        ((float4*)h0)[(size_t)node * 16 + q] =
            ((const float4*)emb)[(size_t)s * 16 + q];
    }
}

// Per-edge scatter: 16 lanes per edge, float4 vector RED into g_sums.
__global__ void scatter_kernel(const float* __restrict__ h,
                               const int* __restrict__ ei,
                               const int* __restrict__ et,
                               int E_, int do_count) {
    int gid  = blockIdx.x * blockDim.x + threadIdx.x;
    int grp  = gid >> 4;
    int lane = gid & 15;
    int ngrp = (gridDim.x * blockDim.x) >> 4;
    for (int e = grp; e < E_; e += ngrp) {
        int src = ei[e];
        int dst = ei[E_ + e];
        int r   = et[e];
        int seg = dst * Rr + r;
        float4 v = ((const float4*)h)[(size_t)src * 16 + lane];
        float* dp = g_sums + ((size_t)seg * Dd) + lane * 4;
        asm volatile("red.global.add.v4.f32 [%0], {%1,%2,%3,%4};"
                     :: "l"(dp), "f"(v.x), "f"(v.y), "f"(v.z), "f"(v.w)
                     : "memory");
        if (do_count && lane == 0) atomicAdd(&g_cnt[seg], 1.0f);
    }
}

__global__ void inv_kernel(int n) {
    int i = blockIdx.x * blockDim.x + threadIdx.x;
    if (i < n) g_cnt[i] = 1.0f / fmaxf(g_cnt[i], 1.0f);
}

// Fused mean-normalize + [N,576]x[576,64] GEMM + bias (+ReLU).
// Layout: k in [0,512) -> (r,d) of W (W is [R,D,D] contiguous so sB = W flat),
//         k in [512,576) -> root rows. A row: [mean | h].
#define KTOT 576
#define SB_ELEMS (KTOT * Dd)     // 36864
#define SA_PITCH 580             // 16B aligned, bank-offset padded
#define NB 32                    // nodes per tile
#define SA_ELEMS (NB * SA_PITCH) // 18560
#define SMEM_FLOATS (SB_ELEMS + Dd + SA_ELEMS)

__global__ __launch_bounds__(256, 1)
void transform_kernel(const float* __restrict__ sums,
                      const float* __restrict__ invc,
                      const float* __restrict__ h,
                      const float* __restrict__ W,
                      const float* __restrict__ root,
                      const float* __restrict__ bias,
                      float* __restrict__ out,
                      int nNodes, int doRelu) {
    extern __shared__ float sm[];
    float* sB    = sm;                  // [576][64]
    float* sbias = sm + SB_ELEMS;       // [64]
    float* sA    = sbias + Dd;          // [32][580]

    int tid = threadIdx.x;
    for (int i = tid; i < 512 * Dd; i += 256) sB[i] = W[i];
    for (int i = tid; i < Dd * Dd; i += 256)  sB[512 * Dd + i] = root[i];
    if (tid < Dd) sbias[tid] = bias[tid];
    __syncthreads();

    int c4   = tid & 15;   // column group: cols [4*c4, 4*c4+4)
    int slot = tid >> 4;   // node slot 0..15; handles nodes slot and slot+16

    int ntiles = (nNodes + NB - 1) / NB;
    for (int tile = blockIdx.x; tile < ntiles; tile += gridDim.x) {
        int n0 = tile * NB;

        // ---- stage A tile: 32 nodes x 144 float4 ----
        for (int i = tid; i < NB * 144; i += 256) {
            int nn = i / 144;
            int k4 = i - nn * 144;
            int n  = n0 + nn;
            float4 v = make_float4(0.f, 0.f, 0.f, 0.f);
            if (n < nNodes) {
                if (k4 < 128) {
                    v = ((const float4*)sums)[(size_t)n * 128 + k4];
                    float s = invc[n * Rr + (k4 >> 4)];
                    v.x *= s; v.y *= s; v.z *= s; v.w *= s;
                } else {
                    v = ((const float4*)h)[(size_t)n * 16 + (k4 - 128)];
                }
            }
            *(float4*)&sA[nn * SA_PITCH + k4 * 4] = v;
        }
        __syncthreads();

        // ---- compute 2 nodes x 4 cols per thread ----
        float4 acc0 = *(const float4*)&sbias[c4 * 4];
        float4 acc1 = acc0;
        const float* pA0 = sA + slot * SA_PITCH;
        const float* pA1 = pA0 + 16 * SA_PITCH;
        const float* pB  = sB + c4 * 4;
        #pragma unroll 8
        for (int k = 0; k < KTOT; ++k) {
            float4 w = *(const float4*)(pB + k * Dd);
            float a0 = pA0[k];
            float a1 = pA1[k];
            acc0.x += a0 * w.x; acc0.y += a0 * w.y;
            acc0.z += a0 * w.z; acc0.w += a0 * w.w;
            acc1.x += a1 * w.x; acc1.y += a1 * w.y;
            acc1.z += a1 * w.z; acc1.w += a1 * w.w;
        }
        if (doRelu) {
            acc0.x = fmaxf(acc0.x, 0.f); acc0.y = fmaxf(acc0.y, 0.f);
            acc0.z = fmaxf(acc0.z, 0.f); acc0.w = fmaxf(acc0.w, 0.f);
            acc1.x = fmaxf(acc1.x, 0.f); acc1.y = fmaxf(acc1.y, 0.f);
            acc1.z = fmaxf(acc1.z, 0.f); acc1.w = fmaxf(acc1.w, 0.f);
        }
        int na = n0 + slot;
        int nb = n0 + slot + 16;
        if (na < nNodes) ((float4*)out)[(size_t)na * 16 + c4] = acc0;
        if (nb < nNodes) ((float4*)out)[(size_t)nb * 16 + c4] = acc1;
        __syncthreads();   // sA reused next tile
    }
}

// ---------------------------------------------------------------------------
extern "C" void kernel_launch(void* const* d_in, const int* in_sizes, int n_in,
                              void* d_out, int out_size) {
    const int*   x    = (const int*)d_in[0];      // int32 (JAX x64 off)
    const int*   ei   = (const int*)d_in[1];      // [2, E] int32
    const int*   et   = (const int*)d_in[2];      // [E]   int32
    const float* emb  = (const float*)d_in[3];
    const float* W1   = (const float*)d_in[4];
    const float* rt1  = (const float*)d_in[5];
    const float* b1   = (const float*)d_in[6];
    const float* W2   = (const float*)d_in[7];
    const float* rt2  = (const float*)d_in[8];
    const float* b2   = (const float*)d_in[9];
    float*       out  = (float*)d_out;

    int n  = in_sizes[0];      // 100000
    int E_ = in_sizes[2];      // 3200000

    void *ps, *pc, *ph0, *ph1;
    cudaGetSymbolAddress(&ps,  g_sums);
    cudaGetSymbolAddress(&pc,  g_cnt);
    cudaGetSymbolAddress(&ph0, g_h0);
    cudaGetSymbolAddress(&ph1, g_h1);
    float* sums = (float*)ps;
    float* cnt  = (float*)pc;
    float* h0   = (float*)ph0;
    float* h1   = (float*)ph1;

    static const size_t smem_bytes = (size_t)SMEM_FLOATS * sizeof(float); // 221,952
    cudaFuncSetAttribute(transform_kernel,
                         cudaFuncAttributeMaxDynamicSharedMemorySize,
                         (int)smem_bytes);

    size_t sums4 = (size_t)n * Rr * Dd / 4;
    size_t cnt4  = (size_t)n * Rr / 4;

    // counts identical for both layers -> compute once
    zero_kernel<<<2048, 256>>>(sums, sums4);
    zero_kernel<<<256,  256>>>(cnt,  cnt4);
    gather_kernel<<<4096, 256>>>(emb, x, h0, n);
    scatter_kernel<<<9472, 256>>>(h0, ei, et, E_, 1);
    inv_kernel<<<(n * Rr + 255) / 256, 256>>>(n * Rr);
    transform_kernel<<<148, 256, smem_bytes>>>(sums, cnt, h0, W1, rt1, b1, h1, n, 1);

    zero_kernel<<<2048, 256>>>(sums, sums4);
    scatter_kernel<<<9472, 256>>>(h1, ei, et, E_, 0);
    transform_kernel<<<148, 256, smem_bytes>>>(sums, cnt, h1, W2, rt2, b2, out, n, 0);
}

// round 4
// speedup vs baseline: 2.0657x; 2.0657x over previous
#include <cuda_runtime.h>
#include <cstdint>

#define Dd 64
#define Rr 8
#define MAXN 100000
#define MAXE 3200000
#define NCHUNK 9                 // 8 relations + root

// Scratch (no allocation allowed). 256B aligned for vector LDG/STG/RED.
__device__ __align__(256) float g_hw[(size_t)NCHUNK * MAXN * Dd]; // 230.4 MB
__device__ __align__(256) float g_cnt[MAXN * Rr];                 // inv counts
__device__ __align__(256) float g_h0[MAXN * Dd];
__device__ __align__(256) float g_h1[MAXN * Dd];

// ---------------------------------------------------------------------------
__global__ void zero_kernel(float* __restrict__ p, size_t n4) {
    size_t i = (size_t)blockIdx.x * blockDim.x + threadIdx.x;
    size_t stride = (size_t)gridDim.x * blockDim.x;
    float4 z = make_float4(0.f, 0.f, 0.f, 0.f);
    for (; i < n4; i += stride) ((float4*)p)[i] = z;
}

// h0[i,:] = emb[x[i],:]
__global__ void gather_kernel(const float* __restrict__ emb,
                              const int* __restrict__ x,
                              float* __restrict__ h0, int n) {
    int total = n * 16;
    int stride = gridDim.x * blockDim.x;
    for (int i = blockIdx.x * blockDim.x + threadIdx.x; i < total; i += stride) {
        int node = i >> 4, q = i & 15;
        ((float4*)h0)[(size_t)node * 16 + q] =
            ((const float4*)emb)[(size_t)x[node] * 16 + q];
    }
}

__global__ void count_kernel(const int* __restrict__ ei,
                             const int* __restrict__ et, int E_) {
    int stride = gridDim.x * blockDim.x;
    for (int e = blockIdx.x * blockDim.x + threadIdx.x; e < E_; e += stride)
        atomicAdd(&g_cnt[ei[E_ + e] * Rr + et[e]], 1.0f);
}

__global__ void inv_kernel(int n) {
    int i = blockIdx.x * blockDim.x + threadIdx.x;
    if (i < n) g_cnt[i] = 1.0f / fmaxf(g_cnt[i], 1.0f);
}

// ---------------------------------------------------------------------------
// GEMM: hw[c][n][:] = A[n][:] @ B_c, A = (relu?)h [N,64], B_c = W[c] (c<8) or root.
// Tile: 64 nodes x 64 cols per block, 256 threads, 4 nodes x 4 cols per thread.
__global__ __launch_bounds__(256)
void gemm_kernel(const float* __restrict__ h,
                 const float* __restrict__ W,     // [8,64,64]
                 const float* __restrict__ root,  // [64,64]
                 float* __restrict__ hw,          // [9,N,64]
                 int nNodes, int doRelu) {
    __shared__ float sA[64][68];   // [k][node]
    __shared__ float sB[64][68];   // [k][col]
    int tid = threadIdx.x;
    int n0 = blockIdx.x * 64;

    // stage A transposed (k-major), optional relu
    for (int i = tid; i < 64 * 16; i += 256) {
        int nn = i >> 4, k4 = i & 15;
        int n = n0 + nn;
        float4 v = make_float4(0.f, 0.f, 0.f, 0.f);
        if (n < nNodes) v = ((const float4*)h)[(size_t)n * 16 + k4];
        if (doRelu) {
            v.x = fmaxf(v.x, 0.f); v.y = fmaxf(v.y, 0.f);
            v.z = fmaxf(v.z, 0.f); v.w = fmaxf(v.w, 0.f);
        }
        sA[k4 * 4 + 0][nn] = v.x; sA[k4 * 4 + 1][nn] = v.y;
        sA[k4 * 4 + 2][nn] = v.z; sA[k4 * 4 + 3][nn] = v.w;
    }

    int c4 = tid & 15;    // col group (4 cols)
    int ng = tid >> 4;    // node group (4 nodes)

    for (int chunk = 0; chunk < NCHUNK; ++chunk) {
        const float* B = (chunk < 8) ? (W + chunk * 4096) : root;
        __syncthreads();   // sB safe to overwrite / sA staged
        for (int i = tid; i < 64 * 16; i += 256) {
            int k = i >> 4, q = i & 15;
            *(float4*)&sB[k][q * 4] = ((const float4*)B)[k * 16 + q];
        }
        __syncthreads();

        float4 a0 = make_float4(0.f, 0.f, 0.f, 0.f);
        float4 a1 = a0, a2 = a0, a3 = a0;
        #pragma unroll
        for (int k = 0; k < 64; ++k) {
            float4 w = *(const float4*)&sB[k][c4 * 4];
            float4 a = *(const float4*)&sA[k][ng * 4];
            a0.x += a.x * w.x; a0.y += a.x * w.y; a0.z += a.x * w.z; a0.w += a.x * w.w;
            a1.x += a.y * w.x; a1.y += a.y * w.y; a1.z += a.y * w.z; a1.w += a.y * w.w;
            a2.x += a.z * w.x; a2.y += a.z * w.y; a2.z += a.z * w.z; a2.w += a.z * w.w;
            a3.x += a.w * w.x; a3.y += a.w * w.y; a3.z += a.w * w.z; a3.w += a.w * w.w;
        }
        float* dst = hw + (size_t)chunk * nNodes * Dd;
        int nb = n0 + ng * 4;
        if (nb + 0 < nNodes) ((float4*)dst)[(size_t)(nb + 0) * 16 + c4] = a0;
        if (nb + 1 < nNodes) ((float4*)dst)[(size_t)(nb + 1) * 16 + c4] = a1;
        if (nb + 2 < nNodes) ((float4*)dst)[(size_t)(nb + 2) * 16 + c4] = a2;
        if (nb + 3 < nNodes) ((float4*)dst)[(size_t)(nb + 3) * 16 + c4] = a3;
    }
}

// out[n] = bias + hw[8][n]   (root term + bias init)
__global__ void init_kernel(const float* __restrict__ hw8,
                            const float* __restrict__ bias,
                            float* __restrict__ out, int n) {
    int total = n * 16;
    int stride = gridDim.x * blockDim.x;
    for (int i = blockIdx.x * blockDim.x + threadIdx.x; i < total; i += stride) {
        int q = i & 15;
        float4 v = ((const float4*)hw8)[i];
        float4 b = ((const float4*)bias)[q];
        v.x += b.x; v.y += b.y; v.z += b.z; v.w += b.w;
        ((float4*)out)[i] = v;
    }
}

// out[dst] += invc[dst*8+rel] * hw[rel][src], 16 lanes (float4) per edge.
__global__ void scatter_kernel(const float* __restrict__ hw,
                               const int* __restrict__ ei,
                               const int* __restrict__ et,
                               float* __restrict__ out, int nNodes, int E_) {
    int gid  = blockIdx.x * blockDim.x + threadIdx.x;
    int grp  = gid >> 4;
    int lane = gid & 15;
    int ngrp = (gridDim.x * blockDim.x) >> 4;
    for (int e = grp; e < E_; e += ngrp) {
        int src = ei[e];
        int dst = ei[E_ + e];
        int r   = et[e];
        float s = g_cnt[dst * Rr + r];
        float4 v = ((const float4*)hw)[((size_t)r * nNodes + src) * 16 + lane];
        v.x *= s; v.y *= s; v.z *= s; v.w *= s;
        float* dp = out + (size_t)dst * Dd + lane * 4;
        asm volatile("red.global.add.v4.f32 [%0], {%1,%2,%3,%4};"
                     :: "l"(dp), "f"(v.x), "f"(v.y), "f"(v.z), "f"(v.w)
                     : "memory");
    }
}

// ---------------------------------------------------------------------------
extern "C" void kernel_launch(void* const* d_in, const int* in_sizes, int n_in,
                              void* d_out, int out_size) {
    const int*   x    = (const int*)d_in[0];
    const int*   ei   = (const int*)d_in[1];
    const int*   et   = (const int*)d_in[2];
    const float* emb  = (const float*)d_in[3];
    const float* W1   = (const float*)d_in[4];
    const float* rt1  = (const float*)d_in[5];
    const float* b1   = (const float*)d_in[6];
    const float* W2   = (const float*)d_in[7];
    const float* rt2  = (const float*)d_in[8];
    const float* b2   = (const float*)d_in[9];
    float*       out  = (float*)d_out;

    int n  = in_sizes[0];
    int E_ = in_sizes[2];

    void *phw, *pc, *ph0, *ph1;
    cudaGetSymbolAddress(&phw, g_hw);
    cudaGetSymbolAddress(&pc,  g_cnt);
    cudaGetSymbolAddress(&ph0, g_h0);
    cudaGetSymbolAddress(&ph1, g_h1);
    float* hw  = (float*)phw;
    float* cnt = (float*)pc;
    float* h0  = (float*)ph0;
    float* h1  = (float*)ph1;

    int gblocks = (n + 63) / 64;

    // edge counts: identical for both layers, compute once
    zero_kernel<<<256, 256>>>(cnt, (size_t)n * Rr / 4);
    gather_kernel<<<2048, 256>>>(emb, x, h0, n);
    count_kernel<<<4096, 256>>>(ei, et, E_);
    inv_kernel<<<(n * Rr + 255) / 256, 256>>>(n * Rr);

    // ---- layer 1 ----
    gemm_kernel<<<gblocks, 256>>>(h0, W1, rt1, hw, n, 0);
    init_kernel<<<2048, 256>>>(hw + (size_t)8 * n * Dd, b1, h1, n);
    scatter_kernel<<<9472, 256>>>(hw, ei, et, h1, n, E_);

    // ---- layer 2 (relu folded into GEMM A-load) ----
    gemm_kernel<<<gblocks, 256>>>(h1, W2, rt2, hw, n, 1);
    init_kernel<<<2048, 256>>>(hw + (size_t)8 * n * Dd, b2, out, n);
    scatter_kernel<<<9472, 256>>>(hw, ei, et, out, n, E_);
}

// round 7
// speedup vs baseline: 2.7858x; 1.3486x over previous
#include <cuda_runtime.h>
#include <cuda_bf16.h>
#include <cstdint>

#define Dd 64
#define Rr 8
#define MAXN 100000
#define NCHUNK 9                  // 8 relations + root

// ---------------- device scratch (no allocation allowed) -------------------
__device__ __align__(256) float    g_hw[(size_t)NCHUNK * MAXN * Dd]; // 230.4MB
__device__ __align__(256) float    g_cnt[MAXN * Rr];
__device__ __align__(256) float    g_h1[MAXN * Dd];
__device__ __align__(256) unsigned g_ahi[MAXN * 32];   // bf16x2-packed A hi
__device__ __align__(256) unsigned g_alo[MAXN * 32];   // bf16x2-packed A lo
__device__ __align__(256) unsigned g_bhi[NCHUNK * 64 * 32]; // [c][n][k-pair]
__device__ __align__(256) unsigned g_blo[NCHUNK * 64 * 32];

// ---------------- small utility kernels ------------------------------------
__global__ void zero_kernel(float* __restrict__ p, size_t n4) {
    size_t i = (size_t)blockIdx.x * blockDim.x + threadIdx.x;
    size_t stride = (size_t)gridDim.x * blockDim.x;
    float4 z = make_float4(0.f, 0.f, 0.f, 0.f);
    for (; i < n4; i += stride) ((float4*)p)[i] = z;
}
__global__ void count_kernel(const int* __restrict__ ei,
                             const int* __restrict__ et, int E_) {
    int stride = gridDim.x * blockDim.x;
    for (int e = blockIdx.x * blockDim.x + threadIdx.x; e < E_; e += stride)
        atomicAdd(&g_cnt[ei[E_ + e] * Rr + et[e]], 1.0f);
}
__global__ void inv_kernel(int n) {
    int i = blockIdx.x * blockDim.x + threadIdx.x;
    if (i < n) g_cnt[i] = 1.0f / fmaxf(g_cnt[i], 1.0f);
}

__device__ __forceinline__ void split2(float a, float b, unsigned& hi, unsigned& lo) {
    __nv_bfloat16 ha = __float2bfloat16_rn(a), hb = __float2bfloat16_rn(b);
    float ra = a - __bfloat162float(ha), rb = b - __bfloat162float(hb);
    __nv_bfloat162 H = __nv_bfloat162(ha, hb);
    __nv_bfloat162 L = __nv_bfloat162(__float2bfloat16_rn(ra), __float2bfloat16_rn(rb));
    hi = *reinterpret_cast<unsigned*>(&H);
    lo = *reinterpret_cast<unsigned*>(&L);
}

// A-split. mode 0: A = emb[x[node]]; mode 1: A = relu(h[node]).
__global__ void splita_kernel(const float* __restrict__ src,
                              const int* __restrict__ x, int n, int mode) {
    int total = n * 32;
    int stride = gridDim.x * blockDim.x;
    for (int j = blockIdx.x * blockDim.x + threadIdx.x; j < total; j += stride) {
        int node = j >> 5, q = j & 31;
        size_t row = (mode == 0) ? (size_t)x[node] : (size_t)node;
        float2 v = ((const float2*)src)[row * 32 + q];
        if (mode == 1) { v.x = fmaxf(v.x, 0.f); v.y = fmaxf(v.y, 0.f); }
        unsigned hi, lo;
        split2(v.x, v.y, hi, lo);
        g_ahi[j] = hi; g_alo[j] = lo;
    }
}

// B-split + transpose: store [c][n][k] (n-major rows) for ldmatrix row.col.
__global__ void splitb_kernel(const float* __restrict__ W,
                              const float* __restrict__ root) {
    int j = blockIdx.x * blockDim.x + threadIdx.x;   // over 9*64*32
    if (j >= NCHUNK * 64 * 32) return;
    int q = j & 31, col = (j >> 5) & 63, c = j >> 11;
    const float* B = (c < 8) ? (W + c * 4096) : root;
    float a = B[(2 * q) * 64 + col];       // k = 2q
    float b = B[(2 * q + 1) * 64 + col];   // k = 2q+1
    unsigned hi, lo;
    split2(a, b, hi, lo);
    g_bhi[j] = hi; g_blo[j] = lo;
}

// ---------------- mma.sync GEMM: hw[c][n][:] = A[n] @ B_c ------------------
// B smem: rows of 72 bf16 (144B pitch) -> ldmatrix conflict-free.
#define BPITCH   144                         // bytes per n-row
#define SB_CHUNK (64 * BPITCH)               // 9216 B per chunk
#define SB_HALF  (NCHUNK * SB_CHUNK)         // 82944 B
#define SB_TOTAL (2 * SB_HALF)               // 165888 B

#define MMA(c0,c1,c2,c3, a, b0, b1)                                            \
    asm volatile("mma.sync.aligned.m16n8k16.row.col.f32.bf16.bf16.f32 "        \
                 "{%0,%1,%2,%3}, {%4,%5,%6,%7}, {%8,%9}, {%0,%1,%2,%3};"       \
                 : "+f"(c0), "+f"(c1), "+f"(c2), "+f"(c3)                      \
                 : "r"((a)[0]), "r"((a)[1]), "r"((a)[2]), "r"((a)[3]),         \
                   "r"(b0), "r"(b1))

#define LDSM_X2(b0, b1, addr)                                                  \
    asm volatile("ldmatrix.sync.aligned.m8n8.x2.shared.b16 {%0,%1}, [%2];"     \
                 : "=r"(b0), "=r"(b1) : "r"(addr))

__global__ __launch_bounds__(512, 1)
void gemm_mma(float* __restrict__ hw, int nNodes) {
    extern __shared__ char sm[];
    int tid = threadIdx.x;

    // stage B hi+lo once per block
    for (int i = tid; i < NCHUNK * 64 * 32; i += 512) {
        int c = i >> 11, col = (i >> 5) & 63, q = i & 31;
        int off = c * SB_CHUNK + col * BPITCH + q * 4;
        *(unsigned*)(sm + off)            = g_bhi[i];
        *(unsigned*)(sm + SB_HALF + off)  = g_blo[i];
    }
    __syncthreads();

    uint32_t smb;
    asm("{ .reg .u64 t; cvta.to.shared.u64 t, %1; cvt.u32.u64 %0, t; }"
        : "=r"(smb) : "l"(sm));

    int warp = tid >> 5, lane = tid & 31;
    int qt = lane & 3;                 // thread column quad
    // per-thread ldmatrix-B base: row (lane&7), k-half ((lane>>3)&1)
    uint32_t bbase = smb + (lane & 7) * BPITCH + ((lane >> 3) & 1) * 16;

    int ntiles = (nNodes + 255) >> 8;
    for (int tile = blockIdx.x; tile < ntiles; tile += gridDim.x) {
        int nbase = tile * 256 + warp * 16;
        int r0 = nbase + (lane >> 2);      // rows for a0/a2
        int r1 = r0 + 8;                   // rows for a1/a3
        bool v0 = r0 < nNodes, v1 = r1 < nNodes;

        // A fragments from global (hi & lo), 4 k-steps
        unsigned ah[4][4], al[4][4];
        #pragma unroll
        for (int s = 0; s < 4; ++s) {
            int i0 = s * 8 + qt;
            ah[s][0] = v0 ? g_ahi[(size_t)r0 * 32 + i0]     : 0u;
            ah[s][1] = v1 ? g_ahi[(size_t)r1 * 32 + i0]     : 0u;
            ah[s][2] = v0 ? g_ahi[(size_t)r0 * 32 + i0 + 4] : 0u;
            ah[s][3] = v1 ? g_ahi[(size_t)r1 * 32 + i0 + 4] : 0u;
            al[s][0] = v0 ? g_alo[(size_t)r0 * 32 + i0]     : 0u;
            al[s][1] = v1 ? g_alo[(size_t)r1 * 32 + i0]     : 0u;
            al[s][2] = v0 ? g_alo[(size_t)r0 * 32 + i0 + 4] : 0u;
            al[s][3] = v1 ? g_alo[(size_t)r1 * 32 + i0 + 4] : 0u;
        }

        for (int c = 0; c < NCHUNK; ++c) {
            uint32_t cb = bbase + c * SB_CHUNK;
            float* dst = hw + (size_t)c * nNodes * Dd;
            #pragma unroll
            for (int j = 0; j < 8; ++j) {          // n8 blocks
                float c0 = 0.f, c1 = 0.f, c2 = 0.f, c3 = 0.f;
                uint32_t jb = cb + j * 8 * BPITCH;
                #pragma unroll
                for (int s = 0; s < 4; ++s) {      // k16 steps
                    unsigned bh0, bh1, bl0, bl1;
                    LDSM_X2(bh0, bh1, jb + s * 32);
                    LDSM_X2(bl0, bl1, jb + s * 32 + SB_HALF);
                    MMA(c0, c1, c2, c3, ah[s], bh0, bh1);
                    MMA(c0, c1, c2, c3, ah[s], bl0, bl1);
                    MMA(c0, c1, c2, c3, al[s], bh0, bh1);
                }
                int col = j * 8 + 2 * qt;
                if (v0) *(float2*)(dst + (size_t)r0 * Dd + col) = make_float2(c0, c1);
                if (v1) *(float2*)(dst + (size_t)r1 * Dd + col) = make_float2(c2, c3);
            }
        }
    }
}

// out[n] = bias + hw[8][n]
__global__ void init_kernel(const float* __restrict__ hw8,
                            const float* __restrict__ bias,
                            float* __restrict__ out, int n) {
    int total = n * 16;
    int stride = gridDim.x * blockDim.x;
    for (int i = blockIdx.x * blockDim.x + threadIdx.x; i < total; i += stride) {
        int q = i & 15;
        float4 v = ((const float4*)hw8)[i];
        float4 b = ((const float4*)bias)[q];
        v.x += b.x; v.y += b.y; v.z += b.z; v.w += b.w;
        ((float4*)out)[i] = v;
    }
}

// out[dst] += invc[dst*8+r] * hw[r][src]
__global__ void scatter_kernel(const float* __restrict__ hw,
                               const int* __restrict__ ei,
                               const int* __restrict__ et,
                               float* __restrict__ out, int nNodes, int E_) {
    int gid  = blockIdx.x * blockDim.x + threadIdx.x;
    int grp  = gid >> 4, lane = gid & 15;
    int ngrp = (gridDim.x * blockDim.x) >> 4;
    for (int e = grp; e < E_; e += ngrp) {
        int src = ei[e], dst = ei[E_ + e], r = et[e];
        float s = g_cnt[dst * Rr + r];
        float4 v = ((const float4*)hw)[((size_t)r * nNodes + src) * 16 + lane];
        v.x *= s; v.y *= s; v.z *= s; v.w *= s;
        float* dp = out + (size_t)dst * Dd + lane * 4;
        asm volatile("red.global.add.v4.f32 [%0], {%1,%2,%3,%4};"
                     :: "l"(dp), "f"(v.x), "f"(v.y), "f"(v.z), "f"(v.w)
                     : "memory");
    }
}

// ---------------------------------------------------------------------------
extern "C" void kernel_launch(void* const* d_in, const int* in_sizes, int n_in,
                              void* d_out, int out_size) {
    const int*   x    = (const int*)d_in[0];
    const int*   ei   = (const int*)d_in[1];
    const int*   et   = (const int*)d_in[2];
    const float* emb  = (const float*)d_in[3];
    const float* W1   = (const float*)d_in[4];
    const float* rt1  = (const float*)d_in[5];
    const float* b1   = (const float*)d_in[6];
    const float* W2   = (const float*)d_in[7];
    const float* rt2  = (const float*)d_in[8];
    const float* b2   = (const float*)d_in[9];
    float*       out  = (float*)d_out;

    int n  = in_sizes[0];
    int E_ = in_sizes[2];

    void *phw, *pc, *ph1;
    cudaGetSymbolAddress(&phw, g_hw);
    cudaGetSymbolAddress(&pc,  g_cnt);
    cudaGetSymbolAddress(&ph1, g_h1);
    float* hw  = (float*)phw;
    float* cnt = (float*)pc;
    float* h1  = (float*)ph1;

    cudaFuncSetAttribute(gemm_mma, cudaFuncAttributeMaxDynamicSharedMemorySize,
                         SB_TOTAL);

    // counts once (identical both layers)
    zero_kernel<<<256, 256>>>(cnt, (size_t)n * Rr / 4);
    count_kernel<<<4096, 256>>>(ei, et, E_);
    inv_kernel<<<(n * Rr + 255) / 256, 256>>>(n * Rr);

    // ---- layer 1 ----
    splitb_kernel<<<(NCHUNK * 64 * 32 + 255) / 256, 256>>>(W1, rt1);
    splita_kernel<<<2048, 256>>>(emb, x, n, 0);
    gemm_mma<<<148, 512, SB_TOTAL>>>(hw, n);
    init_kernel<<<2048, 256>>>(hw + (size_t)8 * n * Dd, b1, h1, n);
    scatter_kernel<<<9472, 256>>>(hw, ei, et, h1, n, E_);

    // ---- layer 2 ----
    splitb_kernel<<<(NCHUNK * 64 * 32 + 255) / 256, 256>>>(W2, rt2);
    splita_kernel<<<2048, 256>>>(h1, nullptr, n, 1);
    gemm_mma<<<148, 512, SB_TOTAL>>>(hw, n);
    init_kernel<<<2048, 256>>>(hw + (size_t)8 * n * Dd, b2, out, n);
    scatter_kernel<<<9472, 256>>>(hw, ei, et, out, n, E_);
}

// round 9
// speedup vs baseline: 3.0183x; 1.0835x over previous
#include <cuda_runtime.h>
#include <cuda_bf16.h>
#include <cstdint>

#define Dd 64
#define Rr 8
#define MAXN 100000
#define MAXE 3200000
#define NCHUNK 9                  // 8 relations + root

// ---------------- device scratch (no allocation allowed) -------------------
__device__ __align__(256) float    g_hw[(size_t)NCHUNK * MAXN * Dd]; // 230.4MB
__device__ __align__(256) float    g_h1[MAXN * Dd];
__device__ __align__(256) unsigned g_ahi[MAXN * 32];   // bf16x2-packed A hi
__device__ __align__(256) unsigned g_alo[MAXN * 32];   // bf16x2-packed A lo
__device__ __align__(256) unsigned g_bhi[NCHUNK * 64 * 32]; // [c][n][k-pair]
__device__ __align__(256) unsigned g_blo[NCHUNK * 64 * 32];
__device__ __align__(256) int      g_base[MAXN * Rr + 1]; // seg offsets (excl scan)
__device__ __align__(256) int      g_cur[MAXN * Rr];      // placement cursors
__device__ __align__(256) int      g_bsum[1024];          // scan block sums
__device__ __align__(256) int      g_ssrc[MAXE];          // seg-sorted src ids

// ---------------- small utility kernels ------------------------------------
__global__ void zeroi_kernel(int* __restrict__ p, int n) {
    int i = blockIdx.x * blockDim.x + threadIdx.x;
    int stride = gridDim.x * blockDim.x;
    for (; i < n; i += stride) p[i] = 0;
}

// histogram over seg = r*N + dst
__global__ void hist_kernel(const int* __restrict__ ei,
                            const int* __restrict__ et, int n, int E_) {
    int stride = gridDim.x * blockDim.x;
    for (int e = blockIdx.x * blockDim.x + threadIdx.x; e < E_; e += stride)
        atomicAdd(&g_base[et[e] * n + ei[E_ + e]], 1);
}

// exclusive scan of g_base[0..S): 3-kernel pass (1024 items / block)
__global__ void scan1_kernel(int S) {
    __shared__ int sh[256];
    int tid = threadIdx.x;
    int i0 = blockIdx.x * 1024 + tid * 4;
    int v[4], t = 0;
    #pragma unroll
    for (int j = 0; j < 4; ++j) {
        int idx = i0 + j;
        v[j] = (idx < S) ? g_base[idx] : 0;
        t += v[j];
    }
    sh[tid] = t;
    __syncthreads();
    for (int off = 1; off < 256; off <<= 1) {
        int x = (tid >= off) ? sh[tid - off] : 0;
        __syncthreads();
        sh[tid] += x;
        __syncthreads();
    }
    int run = sh[tid] - t;   // exclusive prefix of this thread within block
    if (tid == 255) g_bsum[blockIdx.x] = sh[255];
    #pragma unroll
    for (int j = 0; j < 4; ++j) {
        int idx = i0 + j;
        if (idx < S) g_base[idx] = run;
        run += v[j];
    }
}
__global__ void scan2_kernel(int nb) {
    __shared__ int sh[256];
    int tid = threadIdx.x;
    int v[4], t = 0;
    #pragma unroll
    for (int j = 0; j < 4; ++j) {
        int idx = tid * 4 + j;
        v[j] = (idx < nb) ? g_bsum[idx] : 0;
        t += v[j];
    }
    sh[tid] = t;
    __syncthreads();
    for (int off = 1; off < 256; off <<= 1) {
        int x = (tid >= off) ? sh[tid - off] : 0;
        __syncthreads();
        sh[tid] += x;
        __syncthreads();
    }
    int run = sh[tid] - t;
    #pragma unroll
    for (int j = 0; j < 4; ++j) {
        int idx = tid * 4 + j;
        if (idx < nb) g_bsum[idx] = run;
        run += v[j];
    }
}
__global__ void scan3_kernel(int S, int E_) {
    int i = blockIdx.x * blockDim.x + threadIdx.x;
    if (i < S) {
        int b = g_base[i] + g_bsum[i >> 10];
        g_base[i] = b;
        g_cur[i]  = b;
    }
    if (i == 0) g_base[S] = E_;
}

// place edges into seg-sorted order (src only; dst/r implicit in seg)
__global__ void place_kernel(const int* __restrict__ ei,
                             const int* __restrict__ et, int n, int E_) {
    int stride = gridDim.x * blockDim.x;
    for (int e = blockIdx.x * blockDim.x + threadIdx.x; e < E_; e += stride) {
        int seg = et[e] * n + ei[E_ + e];
        int pos = atomicAdd(&g_cur[seg], 1);
        g_ssrc[pos] = ei[e];
    }
}

__device__ __forceinline__ void split2(float a, float b, unsigned& hi, unsigned& lo) {
    __nv_bfloat16 ha = __float2bfloat16_rn(a), hb = __float2bfloat16_rn(b);
    float ra = a - __bfloat162float(ha), rb = b - __bfloat162float(hb);
    __nv_bfloat162 H = __nv_bfloat162(ha, hb);
    __nv_bfloat162 L = __nv_bfloat162(__float2bfloat16_rn(ra), __float2bfloat16_rn(rb));
    hi = *reinterpret_cast<unsigned*>(&H);
    lo = *reinterpret_cast<unsigned*>(&L);
}

// A-split. mode 0: A = emb[x[node]]; mode 1: A = relu(h[node]).
__global__ void splita_kernel(const float* __restrict__ src,
                              const int* __restrict__ x, int n, int mode) {
    int total = n * 32;
    int stride = gridDim.x * blockDim.x;
    for (int j = blockIdx.x * blockDim.x + threadIdx.x; j < total; j += stride) {
        int node = j >> 5, q = j & 31;
        size_t row = (mode == 0) ? (size_t)x[node] : (size_t)node;
        float2 v = ((const float2*)src)[row * 32 + q];
        if (mode == 1) { v.x = fmaxf(v.x, 0.f); v.y = fmaxf(v.y, 0.f); }
        unsigned hi, lo;
        split2(v.x, v.y, hi, lo);
        g_ahi[j] = hi; g_alo[j] = lo;
    }
}

// B-split + transpose: store [c][n][k] (n-major rows) for ldmatrix row.col.
__global__ void splitb_kernel(const float* __restrict__ W,
                              const float* __restrict__ root) {
    int j = blockIdx.x * blockDim.x + threadIdx.x;   // over 9*64*32
    if (j >= NCHUNK * 64 * 32) return;
    int q = j & 31, col = (j >> 5) & 63, c = j >> 11;
    const float* B = (c < 8) ? (W + c * 4096) : root;
    float a = B[(2 * q) * 64 + col];
    float b = B[(2 * q + 1) * 64 + col];
    unsigned hi, lo;
    split2(a, b, hi, lo);
    g_bhi[j] = hi; g_blo[j] = lo;
}

// ---------------- mma.sync GEMM: hw[c][n][:] = A[n] @ B_c ------------------
#define BPITCH   144
#define SB_CHUNK (64 * BPITCH)
#define SB_HALF  (NCHUNK * SB_CHUNK)
#define SB_TOTAL (2 * SB_HALF)   // 165888 B

#define MMA(c0,c1,c2,c3, a, b0, b1)                                            \
    asm volatile("mma.sync.aligned.m16n8k16.row.col.f32.bf16.bf16.f32 "        \
                 "{%0,%1,%2,%3}, {%4,%5,%6,%7}, {%8,%9}, {%0,%1,%2,%3};"       \
                 : "+f"(c0), "+f"(c1), "+f"(c2), "+f"(c3)                      \
                 : "r"((a)[0]), "r"((a)[1]), "r"((a)[2]), "r"((a)[3]),         \
                   "r"(b0), "r"(b1))

#define LDSM_X2(b0, b1, addr)                                                  \
    asm volatile("ldmatrix.sync.aligned.m8n8.x2.shared.b16 {%0,%1}, [%2];"     \
                 : "=r"(b0), "=r"(b1) : "r"(addr))

__global__ __launch_bounds__(512, 1)
void gemm_mma(float* __restrict__ hw, int nNodes) {
    extern __shared__ char sm[];
    int tid = threadIdx.x;

    for (int i = tid; i < NCHUNK * 64 * 32; i += 512) {
        int c = i >> 11, col = (i >> 5) & 63, q = i & 31;
        int off = c * SB_CHUNK + col * BPITCH + q * 4;
        *(unsigned*)(sm + off)           = g_bhi[i];
        *(unsigned*)(sm + SB_HALF + off) = g_blo[i];
    }
    __syncthreads();

    uint32_t smb;
    asm("{ .reg .u64 t; cvta.to.shared.u64 t, %1; cvt.u32.u64 %0, t; }"
        : "=r"(smb) : "l"(sm));

    int warp = tid >> 5, lane = tid & 31;
    int qt = lane & 3;
    uint32_t bbase = smb + (lane & 7) * BPITCH + ((lane >> 3) & 1) * 16;

    int ntiles = (nNodes + 255) >> 8;
    for (int tile = blockIdx.x; tile < ntiles; tile += gridDim.x) {
        int nbase = tile * 256 + warp * 16;
        int r0 = nbase + (lane >> 2);
        int r1 = r0 + 8;
        bool v0 = r0 < nNodes, v1 = r1 < nNodes;

        unsigned ah[4][4], al[4][4];
        #pragma unroll
        for (int s = 0; s < 4; ++s) {
            int i0 = s * 8 + qt;
            ah[s][0] = v0 ? g_ahi[(size_t)r0 * 32 + i0]     : 0u;
            ah[s][1] = v1 ? g_ahi[(size_t)r1 * 32 + i0]     : 0u;
            ah[s][2] = v0 ? g_ahi[(size_t)r0 * 32 + i0 + 4] : 0u;
            ah[s][3] = v1 ? g_ahi[(size_t)r1 * 32 + i0 + 4] : 0u;
            al[s][0] = v0 ? g_alo[(size_t)r0 * 32 + i0]     : 0u;
            al[s][1] = v1 ? g_alo[(size_t)r1 * 32 + i0]     : 0u;
            al[s][2] = v0 ? g_alo[(size_t)r0 * 32 + i0 + 4] : 0u;
            al[s][3] = v1 ? g_alo[(size_t)r1 * 32 + i0 + 4] : 0u;
        }

        for (int c = 0; c < NCHUNK; ++c) {
            uint32_t cb = bbase + c * SB_CHUNK;
            float* dst = hw + (size_t)c * nNodes * Dd;
            #pragma unroll
            for (int j = 0; j < 8; ++j) {
                float c0 = 0.f, c1 = 0.f, c2 = 0.f, c3 = 0.f;
                uint32_t jb = cb + j * 8 * BPITCH;
                #pragma unroll
                for (int s = 0; s < 4; ++s) {
                    unsigned bh0, bh1, bl0, bl1;
                    LDSM_X2(bh0, bh1, jb + s * 32);
                    LDSM_X2(bl0, bl1, jb + s * 32 + SB_HALF);
                    MMA(c0, c1, c2, c3, ah[s], bh0, bh1);
                    MMA(c0, c1, c2, c3, ah[s], bl0, bl1);
                    MMA(c0, c1, c2, c3, al[s], bh0, bh1);
                }
                int col = j * 8 + 2 * qt;
                if (v0) *(float2*)(dst + (size_t)r0 * Dd + col) = make_float2(c0, c1);
                if (v1) *(float2*)(dst + (size_t)r1 * Dd + col) = make_float2(c2, c3);
            }
        }
    }
}

// out[n] = bias + hw[8][n]
__global__ void init_kernel(const float* __restrict__ hw8,
                            const float* __restrict__ bias,
                            float* __restrict__ out, int n) {
    int total = n * 16;
    int stride = gridDim.x * blockDim.x;
    for (int i = blockIdx.x * blockDim.x + threadIdx.x; i < total; i += stride) {
        int q = i & 15;
        float4 v = ((const float4*)hw8)[i];
        float4 b = ((const float4*)bias)[q];
        v.x += b.x; v.y += b.y; v.z += b.z; v.w += b.w;
        ((float4*)out)[i] = v;
    }
}

// per-segment scatter: one 16-lane group per (r,dst) segment; register
// accumulation over the segment's edges, single red.v4 per lane.
__global__ void seg_scatter(const float* __restrict__ hw,
                            float* __restrict__ out, int n) {
    int gid  = blockIdx.x * blockDim.x + threadIdx.x;
    int seg  = gid >> 4, lane = gid & 15;
    int S = n * Rr;
    if (seg >= S) return;
    int s = g_base[seg], e = g_base[seg + 1];
    if (e == s) return;
    int r   = seg / n;
    int dst = seg - r * n;
    const float4* plane = (const float4*)(hw + (size_t)r * n * Dd);
    float4 acc = make_float4(0.f, 0.f, 0.f, 0.f);
    for (int i = s; i < e; ++i) {
        float4 v = plane[(size_t)g_ssrc[i] * 16 + lane];
        acc.x += v.x; acc.y += v.y; acc.z += v.z; acc.w += v.w;
    }
    float sc = 1.0f / (float)(e - s);
    acc.x *= sc; acc.y *= sc; acc.z *= sc; acc.w *= sc;
    float* dp = out + (size_t)dst * Dd + lane * 4;
    asm volatile("red.global.add.v4.f32 [%0], {%1,%2,%3,%4};"
                 :: "l"(dp), "f"(acc.x), "f"(acc.y), "f"(acc.z), "f"(acc.w)
                 : "memory");
}

// ---------------------------------------------------------------------------
extern "C" void kernel_launch(void* const* d_in, const int* in_sizes, int n_in,
                              void* d_out, int out_size) {
    const int*   x    = (const int*)d_in[0];
    const int*   ei   = (const int*)d_in[1];
    const int*   et   = (const int*)d_in[2];
    const float* emb  = (const float*)d_in[3];
    const float* W1   = (const float*)d_in[4];
    const float* rt1  = (const float*)d_in[5];
    const float* b1   = (const float*)d_in[6];
    const float* W2   = (const float*)d_in[7];
    const float* rt2  = (const float*)d_in[8];
    const float* b2   = (const float*)d_in[9];
    float*       out  = (float*)d_out;

    int n  = in_sizes[0];
    int E_ = in_sizes[2];
    int S  = n * Rr;

    void *phw, *ph1, *pb;
    cudaGetSymbolAddress(&phw, g_hw);
    cudaGetSymbolAddress(&ph1, g_h1);
    cudaGetSymbolAddress(&pb,  g_base);
    float* hw   = (float*)phw;
    float* h1   = (float*)ph1;
    int*   base = (int*)pb;

    cudaFuncSetAttribute(gemm_mma, cudaFuncAttributeMaxDynamicSharedMemorySize,
                         SB_TOTAL);

    // ---- one-time edge segment sort: seg = r*N + dst ----
    int nscan = (S + 1023) / 1024;
    zeroi_kernel<<<1024, 256>>>(base, S + 1);
    hist_kernel<<<4096, 256>>>(ei, et, n, E_);
    scan1_kernel<<<nscan, 256>>>(S);
    scan2_kernel<<<1, 256>>>(nscan);
    scan3_kernel<<<(S + 255) / 256, 256>>>(S, E_);
    place_kernel<<<4096, 256>>>(ei, et, n, E_);

    int sblocks = (S * 16 + 255) / 256;

    // ---- layer 1 ----
    splitb_kernel<<<(NCHUNK * 64 * 32 + 255) / 256, 256>>>(W1, rt1);
    splita_kernel<<<2048, 256>>>(emb, x, n, 0);
    gemm_mma<<<148, 512, SB_TOTAL>>>(hw, n);
    init_kernel<<<2048, 256>>>(hw + (size_t)8 * n * Dd, b1, h1, n);
    seg_scatter<<<sblocks, 256>>>(hw, h1, n);

    // ---- layer 2 ----
    splitb_kernel<<<(NCHUNK * 64 * 32 + 255) / 256, 256>>>(W2, rt2);
    splita_kernel<<<2048, 256>>>(h1, nullptr, n, 1);
    gemm_mma<<<148, 512, SB_TOTAL>>>(hw, n);
    init_kernel<<<2048, 256>>>(hw + (size_t)8 * n * Dd, b2, out, n);
    seg_scatter<<<sblocks, 256>>>(hw, out, n);
}